// round 12
// baseline (speedup 1.0000x reference)
#include <cuda_runtime.h>
#include <cuda_fp16.h>
#include <math.h>
#include <stdint.h>

#define N_NODES 50000
#define N_EDGES 600000
#define SCAN_BLOCKS ((N_NODES + 511) / 512)   // 98

// ---------------- scratch (device globals) -----------------------------------
__device__ int      g_deg[N_NODES];
__device__ int      g_cnt2[N_NODES];
__device__ int      g_off[N_NODES + 1];
__device__ int      g_pos[N_NODES];
__device__ int      g_pos2[N_NODES];
__device__ volatile int g_blk_flag[SCAN_BLOCKS];
__device__ volatile int g_blk_agg[SCAN_BLOCKS];
__device__ volatile int g_blk_pref[SCAN_BLOCKS];
__device__ int      g_csr[N_EDGES];
__device__ __half   g_x16 [(size_t)N_NODES * 128];
__device__ __half   g_agg16[(size_t)N_NODES * 256];   // layer2 aggregation only
__device__ __half   g_h16 [(size_t)N_NODES * 256];
__device__ __half   g_y2  [(size_t)N_NODES * 256];
__device__ __half   g_w16 [262144];

#define OFF_W1L 0
#define OFF_W1R 32768
#define OFF_WS  65536
#define OFF_W2L 98304
#define OFF_W2R 163840
#define OFF_WO  229376

// ---------------- fast tanh ----------------------------------------------------
__device__ __forceinline__ float fast_tanh(float x) {
    float xc = fminf(fmaxf(x, -9.f), 9.f);
    float x2 = xc * xc;
    float p = fmaf(x2, -2.76076847742355e-16f, 2.00018790482477e-13f);
    p = fmaf(p, x2, -8.60467152213735e-11f);
    p = fmaf(p, x2, 5.12229709037114e-08f);
    p = fmaf(p, x2, 1.48572235717979e-05f);
    p = fmaf(p, x2, 6.37261928875436e-04f);
    p = fmaf(p, x2, 4.89352455891786e-03f);
    p = p * xc;
    float q = fmaf(x2, 1.19825839466702e-06f, 1.18534705686654e-04f);
    q = fmaf(q, x2, 2.26843463243900e-03f);
    q = fmaf(q, x2, 4.89352518554385e-03f);
    return __fdividef(p, q);
}

// ---------------- zero + conversions -------------------------------------------
__global__ void zero_kernel() {
    int i = blockIdx.x * blockDim.x + threadIdx.x;
    if (i < N_NODES) { g_deg[i] = 0; g_cnt2[i] = 0; }
    if (i < SCAN_BLOCKS) g_blk_flag[i] = 0;
}

__global__ void prep_x_kernel(const float* __restrict__ x) {
    int tid = blockIdx.x * blockDim.x + threadIdx.x;
    int tot = gridDim.x * blockDim.x;
    for (int i = tid; i < N_NODES * 128 / 4; i += tot) {
        float4 v = ((const float4*)x)[i];
        __half2* d = (__half2*)(g_x16 + (size_t)i * 4);
        d[0] = __floats2half2_rn(v.x, v.y);
        d[1] = __floats2half2_rn(v.z, v.w);
    }
}

__global__ void prep_w_kernel(const float* __restrict__ W1l, const float* __restrict__ W1r,
                              const float* __restrict__ Ws,  const float* __restrict__ W2l,
                              const float* __restrict__ W2r, const float* __restrict__ Wo) {
    int tid = blockIdx.x * blockDim.x + threadIdx.x;
    int tot = gridDim.x * blockDim.x;
    const float* srcs[6] = {W1l, W1r, Ws, W2l, W2r, Wo};
    const int    lens[6] = {32768, 32768, 32768, 65536, 65536, 32768};
    const int    offs[6] = {OFF_W1L, OFF_W1R, OFF_WS, OFF_W2L, OFF_W2R, OFF_WO};
#pragma unroll
    for (int s = 0; s < 6; s++) {
        const float4* sp = (const float4*)srcs[s];
        __half2* dp = (__half2*)(g_w16 + offs[s]);
        for (int i = tid; i < lens[s] / 4; i += tot) {
            float4 v = sp[i];
            dp[i * 2]     = __floats2half2_rn(v.x, v.y);
            dp[i * 2 + 1] = __floats2half2_rn(v.z, v.w);
        }
    }
}

// ---------------- CSR build -----------------------------------------------------
__global__ void count_kernel(const int* __restrict__ dst, const unsigned* __restrict__ mask) {
    int e = blockIdx.x * blockDim.x + threadIdx.x;
    if (e >= N_EDGES) return;
    int d = dst[e];
    atomicAdd(&g_deg[d], 1);
    if (mask[e] != 0u) atomicAdd(&g_cnt2[d], 1);
}

__global__ void scan_kernel() {
    __shared__ int sh[512];
    __shared__ int s_prev;
    int b = blockIdx.x, tid = threadIdx.x;
    int i = b * 512 + tid;
    int v = (i < N_NODES) ? g_deg[i] : 0;
    sh[tid] = v;
    __syncthreads();
    for (int o = 1; o < 512; o <<= 1) {
        int t = (tid >= o) ? sh[tid - o] : 0;
        __syncthreads();
        sh[tid] += t;
        __syncthreads();
    }
    int total = sh[511];

    if (tid < 32) {
        if (b == 0) {
            if (tid == 0) {
                g_blk_pref[0] = total;
                __threadfence();
                g_blk_flag[0] = 2;
                s_prev = 0;
            }
        } else {
            if (tid == 0) {
                g_blk_agg[b] = total;
                __threadfence();
                g_blk_flag[b] = 1;
            }
            int run = 0;
            int base = b;
            while (true) {
                int j = base - 32 + tid;
                int f;
                do {
                    f = (j >= 0) ? g_blk_flag[j] : 2;
                } while (__any_sync(0xffffffffu, f == 0));
                __threadfence();
                unsigned pmask = __ballot_sync(0xffffffffu, f == 2);
                if (pmask) {
                    int hi = 31 - __clz(pmask);
                    int contrib = 0;
                    if (tid == hi)      contrib = (j >= 0) ? g_blk_pref[j] : 0;
                    else if (tid > hi)  contrib = g_blk_agg[j];
#pragma unroll
                    for (int o = 16; o; o >>= 1) contrib += __shfl_xor_sync(0xffffffffu, contrib, o);
                    run += contrib;
                    break;
                } else {
                    int contrib = (j >= 0) ? g_blk_agg[j] : 0;
#pragma unroll
                    for (int o = 16; o; o >>= 1) contrib += __shfl_xor_sync(0xffffffffu, contrib, o);
                    run += contrib;
                    base -= 32;
                }
            }
            if (tid == 0) {
                g_blk_pref[b] = run + total;
                __threadfence();
                g_blk_flag[b] = 2;
                s_prev = run;
            }
        }
    }
    __syncthreads();
    int excl = s_prev + sh[tid] - v;
    if (i < N_NODES) {
        g_off[i]  = excl;
        g_pos[i]  = excl;
        g_pos2[i] = excl + g_cnt2[i];
    }
    if (b == 0 && tid == 0) g_off[N_NODES] = N_EDGES;
}

__global__ void scatter_kernel(const int* __restrict__ src, const int* __restrict__ dst,
                               const unsigned* __restrict__ mask) {
    int e = blockIdx.x * blockDim.x + threadIdx.x;
    if (e >= N_EDGES) return;
    int d = dst[e];
    int slot;
    if (mask[e] != 0u) slot = atomicAdd(&g_pos[d], 1);
    else               slot = atomicAdd(&g_pos2[d], 1);
    g_csr[slot] = src[e];
}

// ---------------- aggregation for layer2 ------------------------------------------
__global__ void agg2_kernel() {
    int w    = (blockIdx.x * blockDim.x + threadIdx.x) >> 5;
    int lane = threadIdx.x & 31;
    if (w >= N_NODES) return;
    int beg = g_off[w];
    int c   = g_cnt2[w];
    int end = beg + c;
    float a0[8], a1[8];
#pragma unroll
    for (int j = 0; j < 8; j++) { a0[j] = 0.f; a1[j] = 0.f; }
    int p = beg;
    for (; p + 2 <= end; p += 2) {
        int s0 = g_csr[p], s1 = g_csr[p + 1];
        uint4 t0 = *(const uint4*)(g_h16 + (size_t)s0 * 256 + lane * 8);
        uint4 t1 = *(const uint4*)(g_h16 + (size_t)s1 * 256 + lane * 8);
        float2 f;
        f = __half22float2(*(__half2*)&t0.x); a0[0] += f.x; a0[1] += f.y;
        f = __half22float2(*(__half2*)&t0.y); a0[2] += f.x; a0[3] += f.y;
        f = __half22float2(*(__half2*)&t0.z); a0[4] += f.x; a0[5] += f.y;
        f = __half22float2(*(__half2*)&t0.w); a0[6] += f.x; a0[7] += f.y;
        f = __half22float2(*(__half2*)&t1.x); a1[0] += f.x; a1[1] += f.y;
        f = __half22float2(*(__half2*)&t1.y); a1[2] += f.x; a1[3] += f.y;
        f = __half22float2(*(__half2*)&t1.z); a1[4] += f.x; a1[5] += f.y;
        f = __half22float2(*(__half2*)&t1.w); a1[6] += f.x; a1[7] += f.y;
    }
    if (p < end) {
        int s0 = g_csr[p];
        uint4 t0 = *(const uint4*)(g_h16 + (size_t)s0 * 256 + lane * 8);
        float2 f;
        f = __half22float2(*(__half2*)&t0.x); a0[0] += f.x; a0[1] += f.y;
        f = __half22float2(*(__half2*)&t0.y); a0[2] += f.x; a0[3] += f.y;
        f = __half22float2(*(__half2*)&t0.z); a0[4] += f.x; a0[5] += f.y;
        f = __half22float2(*(__half2*)&t0.w); a0[6] += f.x; a0[7] += f.y;
    }
    float inv = 1.0f / (float)(c > 1 ? c : 1);
    __half2 o0 = __floats2half2_rn((a0[0] + a1[0]) * inv, (a0[1] + a1[1]) * inv);
    __half2 o1 = __floats2half2_rn((a0[2] + a1[2]) * inv, (a0[3] + a1[3]) * inv);
    __half2 o2 = __floats2half2_rn((a0[4] + a1[4]) * inv, (a0[5] + a1[5]) * inv);
    __half2 o3 = __floats2half2_rn((a0[6] + a1[6]) * inv, (a0[7] + a1[7]) * inv);
    uint4 o;
    o.x = *(unsigned*)&o0; o.y = *(unsigned*)&o1;
    o.z = *(unsigned*)&o2; o.w = *(unsigned*)&o3;
    *(uint4*)(g_agg16 + (size_t)w * 256 + lane * 8) = o;
}

// ---------------- mma helpers ----------------------------------------------------
__device__ __forceinline__ void mma16(float* d, const unsigned* a, const unsigned* b) {
    asm volatile(
        "mma.sync.aligned.m16n8k16.row.col.f32.f16.f16.f32 "
        "{%0,%1,%2,%3}, {%4,%5,%6,%7}, {%8,%9}, {%0,%1,%2,%3};"
        : "+f"(d[0]), "+f"(d[1]), "+f"(d[2]), "+f"(d[3])
        : "r"(a[0]), "r"(a[1]), "r"(a[2]), "r"(a[3]), "r"(b[0]), "r"(b[1]));
}

__device__ __forceinline__ void ldsm4(unsigned* r, uint32_t addr) {
    asm volatile("ldmatrix.sync.aligned.m8n8.x4.shared.b16 {%0,%1,%2,%3}, [%4];"
        : "=r"(r[0]), "=r"(r[1]), "=r"(r[2]), "=r"(r[3]) : "r"(addr));
}

__device__ __forceinline__ uint32_t smem_u32(const void* p) {
    uint32_t a;
    asm("{ .reg .u64 t; cvta.to.shared.u64 t, %1; cvt.u32.u64 %0, t; }" : "=r"(a) : "l"(p));
    return a;
}

__device__ __forceinline__ void cp16(uint32_t dst, const void* src) {
    asm volatile("cp.async.cg.shared.global [%0], [%1], 16;" :: "r"(dst), "l"(src));
}
__device__ __forceinline__ void cp16z(uint32_t dst, const void* src, int sz) {
    asm volatile("cp.async.cg.shared.global [%0], [%1], 16, %2;" :: "r"(dst), "l"(src), "r"(sz));
}
#define CP_COMMIT() asm volatile("cp.async.commit_group;" ::: "memory")
#define CP_WAIT(n)  asm volatile("cp.async.wait_group %0;" :: "n"(n) : "memory")

#define STG_HALVES 55296
#define STG_A2     9216
#define STG_WL     18432
#define STG_WR     36864
#define FUSE_RS    264        // h2/Wo smem row stride in halves
#define FUSE_WO_OFF 67584     // byte offset of Wo tile within stage area

// layer1 fused layout (halves): A1G[0,18432) A2[18432,36864) Wl[36864,73728) Wr[73728,110592)
#define L1_A2  18432
#define L1_WL  36864
#define L1_WR  73728

__device__ __forceinline__ void cpA128(uint32_t sbase, const __half* __restrict__ g,
                                       int ld, int k0, int row0) {
    int tid = threadIdx.x;
#pragma unroll
    for (int it = 0; it < 2; it++) {
        int idx = it * 512 + tid;
        int r = idx >> 3, cg = idx & 7;
        int gr = row0 + r;
        int rr = gr < N_NODES ? gr : N_NODES - 1;
        int sz = gr < N_NODES ? 16 : 0;
        cp16z(sbase + (r * 72 + cg * 8) * 2, g + (size_t)rr * ld + k0 + cg * 8, sz);
    }
}
__device__ __forceinline__ void cpW256(uint32_t sbase, const __half* __restrict__ g,
                                       int ld, int k0) {
    int tid = threadIdx.x;
#pragma unroll
    for (int it = 0; it < 4; it++) {
        int idx = it * 512 + tid;
        int r = idx >> 3, cg = idx & 7;
        cp16(sbase + (r * 72 + cg * 8) * 2, g + (size_t)r * ld + k0 + cg * 8);
    }
}

// ---------------- layer1: fused gather + GEMM + norm + skip + tanh ----------------
// A1 = mean_{e in N(row)} x16[src]: gathered in-kernel into smem (chunked layout).
// H = tanh( norm(A1@W1l^T + x@W1r^T + b1) + Y2 )
__global__ __launch_bounds__(512, 1) void layer1_fused(
    const __half* __restrict__ X,
    const __half* __restrict__ Wl, const __half* __restrict__ Wr,
    const float* __restrict__ bias,
    const __half* __restrict__ Y2, __half* __restrict__ H)
{
    extern __shared__ char smraw[];
    float*  sB    = (float*)smraw;              // 256
    float*  sred  = sB + 256;                   // 512
    __half* stg   = (__half*)(sred + 512);      // 110592 halves
    uint32_t stg_u = smem_u32(stg);

    int tid = threadIdx.x, lane = tid & 31, w = tid >> 5;
    int wm = w >> 2, wn = w & 3;
    int g = lane >> 2, t = lane & 3;
    int row0 = blockIdx.x * 128;
    const int K = 128;

    if (tid < 256) sB[tid] = bias[tid];

    // load everything (A2=x rows, Wl, Wr for both K-chunks) via cp.async
#pragma unroll
    for (int c = 0; c < 2; c++) {
        cpA128(stg_u + (L1_A2 + c * 9216) * 2, X, K, c * 64, row0);
        cpW256(stg_u + (L1_WL + c * 18432) * 2, Wl, K, c * 64);
        cpW256(stg_u + (L1_WR + c * 18432) * 2, Wr, K, c * 64);
    }
    CP_COMMIT();

    // gather A1 (mean over in-edges) into smem while cp.async flies.
    // warp w handles nodes row0 + w*8 .. +7; lane covers 4 halves at col lane*4.
    {
        int chunk = lane >> 4;                  // 0 or 1 (cols 0-63 / 64-127)
        int ccol  = (lane * 4) & 63;
        for (int i = 0; i < 8; i++) {
            int r = w * 8 + i;
            int node = row0 + r;
            float4 acc0 = make_float4(0.f, 0.f, 0.f, 0.f);
            float4 acc1 = make_float4(0.f, 0.f, 0.f, 0.f);
            int deg = 1;
            if (node < N_NODES) {
                int beg = g_off[node], end = g_off[node + 1];
                deg = end - beg;
                int p = beg;
                for (; p + 2 <= end; p += 2) {
                    int s0 = g_csr[p], s1 = g_csr[p + 1];
                    uint2 t0 = *(const uint2*)(X + (size_t)s0 * 128 + lane * 4);
                    uint2 t1 = *(const uint2*)(X + (size_t)s1 * 128 + lane * 4);
                    float2 a = __half22float2(*(__half2*)&t0.x);
                    float2 b = __half22float2(*(__half2*)&t0.y);
                    float2 cc = __half22float2(*(__half2*)&t1.x);
                    float2 d = __half22float2(*(__half2*)&t1.y);
                    acc0.x += a.x; acc0.y += a.y; acc0.z += b.x; acc0.w += b.y;
                    acc1.x += cc.x; acc1.y += cc.y; acc1.z += d.x; acc1.w += d.y;
                }
                if (p < end) {
                    int s0 = g_csr[p];
                    uint2 t0 = *(const uint2*)(X + (size_t)s0 * 128 + lane * 4);
                    float2 a = __half22float2(*(__half2*)&t0.x);
                    float2 b = __half22float2(*(__half2*)&t0.y);
                    acc0.x += a.x; acc0.y += a.y; acc0.z += b.x; acc0.w += b.y;
                }
            }
            float inv = 1.0f / (float)(deg > 1 ? deg : 1);
            __half2 o0 = __floats2half2_rn((acc0.x + acc1.x) * inv, (acc0.y + acc1.y) * inv);
            __half2 o1 = __floats2half2_rn((acc0.z + acc1.z) * inv, (acc0.w + acc1.w) * inv);
            __half2* dp = (__half2*)(stg + chunk * 9216 + r * 72 + ccol);
            dp[0] = o0;
            dp[1] = o1;
        }
    }
    CP_WAIT(0);
    __syncthreads();

    float acc[2][8][4];
#pragma unroll
    for (int mt = 0; mt < 2; mt++)
#pragma unroll
        for (int nt = 0; nt < 8; nt++)
#pragma unroll
            for (int j = 0; j < 4; j++) acc[mt][nt][j] = 0.f;

    int aRow = 32 * wm + (lane & 15);
    int aCol = (lane >> 4) * 8;
    int bRow = 64 * wn + (lane & 7) + ((lane >> 4) << 3);
    int bCol = ((lane >> 3) & 1) * 8;

#pragma unroll
    for (int c = 0; c < 2; c++) {
#pragma unroll
        for (int ks = 0; ks < 4; ks++) {
            unsigned a1f[2][4], a2f[2][4];
#pragma unroll
            for (int mt = 0; mt < 2; mt++) {
                uint32_t off = ((aRow + 16 * mt) * 72 + ks * 16 + aCol) * 2;
                ldsm4(a1f[mt], stg_u + c * 9216 * 2 + off);
                ldsm4(a2f[mt], stg_u + (L1_A2 + c * 9216) * 2 + off);
            }
#pragma unroll
            for (int ng = 0; ng < 4; ng++) {
                unsigned bl[4], br[4];
                uint32_t off = ((bRow + 16 * ng) * 72 + ks * 16 + bCol) * 2;
                ldsm4(bl, stg_u + (L1_WL + c * 18432) * 2 + off);
                ldsm4(br, stg_u + (L1_WR + c * 18432) * 2 + off);
#pragma unroll
                for (int half = 0; half < 2; half++) {
                    int nt = 2 * ng + half;
                    mma16(acc[0][nt], a1f[0], bl + 2 * half);
                    mma16(acc[0][nt], a2f[0], br + 2 * half);
                    mma16(acc[1][nt], a1f[1], bl + 2 * half);
                    mma16(acc[1][nt], a2f[1], br + 2 * half);
                }
            }
        }
    }
    __syncthreads();

    // bias + per-row sum of squares
#pragma unroll
    for (int mt = 0; mt < 2; mt++) {
        float s0 = 0.f, s1 = 0.f;
#pragma unroll
        for (int nt = 0; nt < 8; nt++) {
            int col = 64 * wn + 8 * nt + 2 * t;
            acc[mt][nt][0] += sB[col];
            acc[mt][nt][1] += sB[col + 1];
            acc[mt][nt][2] += sB[col];
            acc[mt][nt][3] += sB[col + 1];
            s0 += acc[mt][nt][0] * acc[mt][nt][0] + acc[mt][nt][1] * acc[mt][nt][1];
            s1 += acc[mt][nt][2] * acc[mt][nt][2] + acc[mt][nt][3] * acc[mt][nt][3];
        }
        s0 += __shfl_xor_sync(0xffffffffu, s0, 1);
        s0 += __shfl_xor_sync(0xffffffffu, s0, 2);
        s1 += __shfl_xor_sync(0xffffffffu, s1, 1);
        s1 += __shfl_xor_sync(0xffffffffu, s1, 2);
        if (t == 0) {
            int r = 32 * wm + 16 * mt + g;
            sred[r * 4 + wn] = s0;
            sred[(r + 8) * 4 + wn] = s1;
        }
    }
    __syncthreads();

#pragma unroll
    for (int mt = 0; mt < 2; mt++) {
        int r0 = 32 * wm + 16 * mt + g, r1 = r0 + 8;
        float n0 = sred[r0 * 4] + sred[r0 * 4 + 1] + sred[r0 * 4 + 2] + sred[r0 * 4 + 3];
        float n1 = sred[r1 * 4] + sred[r1 * 4 + 1] + sred[r1 * 4 + 2] + sred[r1 * 4 + 3];
        float inv0 = rsqrtf(fmaxf(n0, 1e-24f));
        float inv1 = rsqrtf(fmaxf(n1, 1e-24f));
        int gr0 = row0 + r0, gr1 = row0 + r1;
#pragma unroll
        for (int nt = 0; nt < 8; nt++) {
            int col = 64 * wn + 8 * nt + 2 * t;
            if (gr0 < N_NODES) {
                float v0 = acc[mt][nt][0] * inv0, v1 = acc[mt][nt][1] * inv0;
                float2 f = __half22float2(*(const __half2*)(Y2 + (size_t)gr0 * 256 + col));
                v0 += f.x; v1 += f.y;
                *(__half2*)(H + (size_t)gr0 * 256 + col) =
                    __floats2half2_rn(fast_tanh(v0), fast_tanh(v1));
            }
            if (gr1 < N_NODES) {
                float v2 = acc[mt][nt][2] * inv1, v3 = acc[mt][nt][3] * inv1;
                float2 f = __half22float2(*(const __half2*)(Y2 + (size_t)gr1 * 256 + col));
                v2 += f.x; v3 += f.y;
                *(__half2*)(H + (size_t)gr1 * 256 + col) =
                    __floats2half2_rn(fast_tanh(v2), fast_tanh(v3));
            }
        }
    }
}

// ---------------- layer2 fused (R11 proven): GEMM + norm + tanh + out GEMM --------
__global__ __launch_bounds__(512, 1) void layer2_fused(
    const __half* __restrict__ A1, const __half* __restrict__ A2,
    const __half* __restrict__ Wl, const __half* __restrict__ Wr,
    const float* __restrict__ bias,
    const __half* __restrict__ Wo, const float* __restrict__ bo,
    float* __restrict__ O)
{
    extern __shared__ char smraw[];
    float*  sB    = (float*)smraw;              // 256
    float*  sred  = sB + 256;                   // 512
    float*  sBO   = sred + 512;                 // 128
    __half* stg   = (__half*)(sBO + 128);       // 2 stages x 55296 halves
    uint32_t stg_u = smem_u32(stg);

    int tid = threadIdx.x, lane = tid & 31, w = tid >> 5;
    int wm = w >> 2, wn = w & 3;
    int g = lane >> 2, t = lane & 3;
    int row0 = blockIdx.x * 128;
    const int K = 256;

    if (tid < 256) sB[tid] = bias[tid];
    if (tid < 128) sBO[tid] = bo[tid];

    float acc[2][8][4];
#pragma unroll
    for (int mt = 0; mt < 2; mt++)
#pragma unroll
        for (int nt = 0; nt < 8; nt++)
#pragma unroll
            for (int j = 0; j < 4; j++) acc[mt][nt][j] = 0.f;

    int aRow = 32 * wm + (lane & 15);
    int aCol = (lane >> 4) * 8;
    int bRow = 64 * wn + (lane & 7) + ((lane >> 4) << 3);
    int bCol = ((lane >> 3) & 1) * 8;

    cpA128(stg_u, A1, K, 0, row0);
    cpA128(stg_u + STG_A2 * 2, A2, K, 0, row0);
    cpW256(stg_u + STG_WL * 2, Wl, K, 0);
    cpW256(stg_u + STG_WR * 2, Wr, K, 0);
    CP_COMMIT();

#pragma unroll
    for (int c = 0; c < 4; c++) {
        uint32_t cur = stg_u + (c & 1) * STG_HALVES * 2;
        if (c + 1 < 4) {
            uint32_t nxt = stg_u + ((c + 1) & 1) * STG_HALVES * 2;
            int k0 = (c + 1) << 6;
            cpA128(nxt, A1, K, k0, row0);
            cpA128(nxt + STG_A2 * 2, A2, K, k0, row0);
            cpW256(nxt + STG_WL * 2, Wl, K, k0);
            cpW256(nxt + STG_WR * 2, Wr, K, k0);
            CP_COMMIT();
            CP_WAIT(1);
        } else {
            CP_WAIT(0);
        }
        __syncthreads();

#pragma unroll
        for (int ks = 0; ks < 4; ks++) {
            unsigned a1f[2][4], a2f[2][4];
#pragma unroll
            for (int mt = 0; mt < 2; mt++) {
                uint32_t ad = cur + ((aRow + 16 * mt) * 72 + ks * 16 + aCol) * 2;
                ldsm4(a1f[mt], ad);
                ldsm4(a2f[mt], ad + STG_A2 * 2);
            }
#pragma unroll
            for (int ng = 0; ng < 4; ng++) {
                unsigned bl[4], br[4];
                uint32_t bd = cur + ((bRow + 16 * ng) * 72 + ks * 16 + bCol) * 2;
                ldsm4(bl, bd + STG_WL * 2);
                ldsm4(br, bd + STG_WR * 2);
#pragma unroll
                for (int half = 0; half < 2; half++) {
                    int nt = 2 * ng + half;
                    mma16(acc[0][nt], a1f[0], bl + 2 * half);
                    mma16(acc[0][nt], a2f[0], br + 2 * half);
                    mma16(acc[1][nt], a1f[1], bl + 2 * half);
                    mma16(acc[1][nt], a2f[1], br + 2 * half);
                }
            }
        }
        __syncthreads();
    }

    // start Wo load into dead stage area while we do the norm epilogue
#pragma unroll
    for (int it = 0; it < 8; it++) {
        int idx = it * 512 + tid;
        int r = idx >> 5, cg = idx & 31;
        cp16(stg_u + FUSE_WO_OFF + (r * FUSE_RS + cg * 8) * 2,
             Wo + (size_t)r * 256 + cg * 8);
    }
    CP_COMMIT();

#pragma unroll
    for (int mt = 0; mt < 2; mt++) {
        float s0 = 0.f, s1 = 0.f;
#pragma unroll
        for (int nt = 0; nt < 8; nt++) {
            int col = 64 * wn + 8 * nt + 2 * t;
            acc[mt][nt][0] += sB[col];
            acc[mt][nt][1] += sB[col + 1];
            acc[mt][nt][2] += sB[col];
            acc[mt][nt][3] += sB[col + 1];
            s0 += acc[mt][nt][0] * acc[mt][nt][0] + acc[mt][nt][1] * acc[mt][nt][1];
            s1 += acc[mt][nt][2] * acc[mt][nt][2] + acc[mt][nt][3] * acc[mt][nt][3];
        }
        s0 += __shfl_xor_sync(0xffffffffu, s0, 1);
        s0 += __shfl_xor_sync(0xffffffffu, s0, 2);
        s1 += __shfl_xor_sync(0xffffffffu, s1, 1);
        s1 += __shfl_xor_sync(0xffffffffu, s1, 2);
        if (t == 0) {
            int r = 32 * wm + 16 * mt + g;
            sred[r * 4 + wn] = s0;
            sred[(r + 8) * 4 + wn] = s1;
        }
    }
    __syncthreads();

#pragma unroll
    for (int mt = 0; mt < 2; mt++) {
        int r0 = 32 * wm + 16 * mt + g, r1 = r0 + 8;
        float n0 = sred[r0 * 4] + sred[r0 * 4 + 1] + sred[r0 * 4 + 2] + sred[r0 * 4 + 3];
        float n1 = sred[r1 * 4] + sred[r1 * 4 + 1] + sred[r1 * 4 + 2] + sred[r1 * 4 + 3];
        float inv0 = rsqrtf(fmaxf(n0, 1e-24f));
        float inv1 = rsqrtf(fmaxf(n1, 1e-24f));
#pragma unroll
        for (int nt = 0; nt < 8; nt++) {
            int col = 64 * wn + 8 * nt + 2 * t;
            float v0 = acc[mt][nt][0] * inv0, v1 = acc[mt][nt][1] * inv0;
            float v2 = acc[mt][nt][2] * inv1, v3 = acc[mt][nt][3] * inv1;
            *(__half2*)((char*)stg + (r0 * FUSE_RS + col) * 2) =
                __floats2half2_rn(fast_tanh(v0), fast_tanh(v1));
            *(__half2*)((char*)stg + (r1 * FUSE_RS + col) * 2) =
                __floats2half2_rn(fast_tanh(v2), fast_tanh(v3));
        }
    }

    CP_WAIT(0);
    __syncthreads();

    float acc2[2][4][4];
#pragma unroll
    for (int mt = 0; mt < 2; mt++)
#pragma unroll
        for (int nt = 0; nt < 4; nt++)
#pragma unroll
            for (int j = 0; j < 4; j++) acc2[mt][nt][j] = 0.f;

    int bRow2 = 32 * wn + (lane & 7) + ((lane >> 4) << 3);
    int bCol2 = ((lane >> 3) & 1) * 8;

#pragma unroll
    for (int ks = 0; ks < 16; ks++) {
        unsigned af[2][4];
#pragma unroll
        for (int mt = 0; mt < 2; mt++)
            ldsm4(af[mt], stg_u + ((aRow + 16 * mt) * FUSE_RS + ks * 16 + aCol) * 2);
#pragma unroll
        for (int ng = 0; ng < 2; ng++) {
            unsigned bf[4];
            ldsm4(bf, stg_u + FUSE_WO_OFF +
                      ((bRow2 + 16 * ng) * FUSE_RS + ks * 16 + bCol2) * 2);
#pragma unroll
            for (int half = 0; half < 2; half++) {
                int nt = 2 * ng + half;
                mma16(acc2[0][nt], af[0], bf + 2 * half);
                mma16(acc2[1][nt], af[1], bf + 2 * half);
            }
        }
    }

#pragma unroll
    for (int mt = 0; mt < 2; mt++) {
        int gr0 = row0 + 32 * wm + 16 * mt + g, gr1 = gr0 + 8;
#pragma unroll
        for (int nt = 0; nt < 4; nt++) {
            int col = 32 * wn + 8 * nt + 2 * t;
            float b0 = sBO[col], b1 = sBO[col + 1];
            if (gr0 < N_NODES)
                *(float2*)(O + (size_t)gr0 * 128 + col) =
                    make_float2(acc2[mt][nt][0] + b0, acc2[mt][nt][1] + b1);
            if (gr1 < N_NODES)
                *(float2*)(O + (size_t)gr1 * 128 + col) =
                    make_float2(acc2[mt][nt][2] + b0, acc2[mt][nt][3] + b1);
        }
    }
}

// ---------------- legacy smem loader for skip ------------------------------------
template <int ROWS>
__device__ __forceinline__ void load16(__half* s, const __half* __restrict__ g,
                                       int ld, int k0, int row0, int maxrow) {
    int tid = threadIdx.x;
#pragma unroll
    for (int it = 0; it < ROWS / 32; ++it) {
        int idx = it * 256 + tid;
        int r = idx >> 3, sg = idx & 7;
        uint4 v = make_uint4(0, 0, 0, 0);
        if (row0 + r < maxrow) v = *(const uint4*)(g + (size_t)(row0 + r) * ld + k0 + sg * 8);
        *(uint4*)(s + r * 72 + sg * 8) = v;
    }
}

// ---------------- skip GEMM (off-path) -------------------------------------------
__global__ __launch_bounds__(256, 2) void skip_mma(
    const __half* __restrict__ A, const __half* __restrict__ W,
    const float* __restrict__ bias, __half* __restrict__ Y)
{
    extern __shared__ char smraw[];
    float*  sB = (float*)smraw;
    __half* sA = (__half*)(sB + 256);
    __half* sW = sA + 64 * 72;

    int tid = threadIdx.x, lane = tid & 31, w = tid >> 5;
    int wm = w >> 2, wn = w & 3;
    int g = lane >> 2, t = lane & 3;
    int row0 = blockIdx.x * 64;
    const int K = 128;

    if (tid < 256) sB[tid] = bias[tid];

    float acc[2][8][4];
#pragma unroll
    for (int mt = 0; mt < 2; mt++)
#pragma unroll
        for (int nt = 0; nt < 8; nt++)
#pragma unroll
            for (int j = 0; j < 4; j++) acc[mt][nt][j] = 0.f;

    for (int c = 0; c < 2; c++) {
        int k0 = c << 6;
        load16<64>(sA, A, K, k0, row0, N_NODES);
        load16<256>(sW, W, K, k0, 0, 256);
        __syncthreads();
        const unsigned* uA = (const unsigned*)sA;
        const unsigned* uW = (const unsigned*)sW;
#pragma unroll
        for (int ks = 0; ks < 4; ks++) {
            int wb = ks * 8 + t;
            unsigned af[2][4];
#pragma unroll
            for (int mt = 0; mt < 2; mt++) {
                int r = 32 * wm + 16 * mt + g;
                af[mt][0] = uA[r * 36 + wb];
                af[mt][1] = uA[(r + 8) * 36 + wb];
                af[mt][2] = uA[r * 36 + wb + 4];
                af[mt][3] = uA[(r + 8) * 36 + wb + 4];
            }
#pragma unroll
            for (int nt = 0; nt < 8; nt++) {
                int n = 64 * wn + 8 * nt + g;
                unsigned bf[2];
                bf[0] = uW[n * 36 + wb]; bf[1] = uW[n * 36 + wb + 4];
                mma16(acc[0][nt], af[0], bf);
                mma16(acc[1][nt], af[1], bf);
            }
        }
        __syncthreads();
    }

#pragma unroll
    for (int mt = 0; mt < 2; mt++) {
        int gr0 = row0 + 32 * wm + 16 * mt + g, gr1 = gr0 + 8;
#pragma unroll
        for (int nt = 0; nt < 8; nt++) {
            int col = 64 * wn + 8 * nt + 2 * t;
            float b0 = sB[col], b1 = sB[col + 1];
            if (gr0 < N_NODES) {
                *(__half2*)(Y + (size_t)gr0 * 256 + col) =
                    __floats2half2_rn(acc[mt][nt][0] + b0, acc[mt][nt][1] + b1);
            }
            if (gr1 < N_NODES) {
                *(__half2*)(Y + (size_t)gr1 * 256 + col) =
                    __floats2half2_rn(acc[mt][nt][2] + b0, acc[mt][nt][3] + b1);
            }
        }
    }
}

// ---------------- launch ----------------------------------------------------------
extern "C" void kernel_launch(void* const* d_in, const int* in_sizes, int n_in,
                              void* d_out, int out_size)
{
    (void)in_sizes; (void)n_in; (void)out_size;
    const float*    x    = (const float*)d_in[0];
    const int*      ei   = (const int*)d_in[1];
    const unsigned* mask = (const unsigned*)d_in[2];
    const float*    W1l  = (const float*)d_in[3];
    const float*    b1   = (const float*)d_in[4];
    const float*    W1r  = (const float*)d_in[5];
    const float*    Ws   = (const float*)d_in[6];
    const float*    bs   = (const float*)d_in[7];
    const float*    W2l  = (const float*)d_in[8];
    const float*    b2   = (const float*)d_in[9];
    const float*    W2r  = (const float*)d_in[10];
    const float*    Wo   = (const float*)d_in[11];
    const float*    bo   = (const float*)d_in[12];
    float*          out  = (float*)d_out;

    const int* src = ei;
    const int* dst = ei + N_EDGES;

    void *p_x16, *p_agg, *p_h, *p_y2, *p_w;
    cudaGetSymbolAddress(&p_x16, g_x16);
    cudaGetSymbolAddress(&p_agg, g_agg16);
    cudaGetSymbolAddress(&p_h,   g_h16);
    cudaGetSymbolAddress(&p_y2,  g_y2);
    cudaGetSymbolAddress(&p_w,   g_w16);
    __half* x16 = (__half*)p_x16;
    __half* agg = (__half*)p_agg;
    __half* h   = (__half*)p_h;
    __half* y2  = (__half*)p_y2;
    __half* w16 = (__half*)p_w;

    static cudaStream_t sB = nullptr;
    static cudaEvent_t evFork = nullptr, evSkip = nullptr;
    if (!sB) {
        cudaStreamCreateWithFlags(&sB, cudaStreamNonBlocking);
        cudaEventCreateWithFlags(&evFork, cudaEventDisableTiming);
        cudaEventCreateWithFlags(&evSkip, cudaEventDisableTiming);
    }

    const int SM_L1   = (256 + 512) * 4 + 110592 * 2;               // 3072 + 221184 = 224256
    const int SM_L2   = (256 + 512 + 128) * 4 + 2 * STG_HALVES * 2; // 3584 + 221184 = 224768
    const int SM_SKIP = 256 * 4 + (64 * 72 + 256 * 72) * 2;
    cudaFuncSetAttribute(layer1_fused, cudaFuncAttributeMaxDynamicSharedMemorySize, SM_L1);
    cudaFuncSetAttribute(layer2_fused, cudaFuncAttributeMaxDynamicSharedMemorySize, SM_L2);
    cudaFuncSetAttribute(skip_mma,     cudaFuncAttributeMaxDynamicSharedMemorySize, SM_SKIP);

    int nb_nodes = (N_NODES + 255) / 256;
    int nb_edges = (N_EDGES + 255) / 256;
    int nb_warps = (N_NODES * 32 + 255) / 256;
    int nb_m64   = (N_NODES + 63) / 64;     // 782
    int nb_m128  = (N_NODES + 127) / 128;   // 391

    // fork: stream B does fp16 conversions + skip GEMM while stream 0 builds CSR
    cudaEventRecord(evFork, 0);
    cudaStreamWaitEvent(sB, evFork, 0);

    prep_x_kernel<<<512, 256, 0, sB>>>(x);
    prep_w_kernel<<<512, 256, 0, sB>>>(W1l, W1r, Ws, W2l, W2r, Wo);
    skip_mma<<<nb_m64, 256, SM_SKIP, sB>>>(x16, w16 + OFF_WS, bs, y2);
    cudaEventRecord(evSkip, sB);

    // stream 0: CSR build
    zero_kernel<<<nb_nodes, 256>>>();
    count_kernel<<<nb_edges, 256>>>(dst, mask);
    scan_kernel<<<SCAN_BLOCKS, 512>>>();
    scatter_kernel<<<nb_edges, 256>>>(src, dst, mask);

    // layer 1 (fused gather + GEMM + norm + skip + tanh)
    cudaStreamWaitEvent(0, evSkip, 0);
    layer1_fused<<<nb_m128, 512, SM_L1>>>(x16, w16 + OFF_W1L, w16 + OFF_W1R, b1, y2, h);

    // layer 2 (agg2 then fused GEMM + norm + tanh + out GEMM)
    agg2_kernel<<<nb_warps, 256>>>();
    layer2_fused<<<nb_m128, 512, SM_L2>>>(
        agg, h, w16 + OFF_W2L, w16 + OFF_W2R, b2, w16 + OFF_WO, bo, out);
}

// round 14
// speedup vs baseline: 1.1764x; 1.1764x over previous
#include <cuda_runtime.h>
#include <cuda_fp16.h>
#include <math.h>
#include <stdint.h>

#define N_NODES 50000
#define N_EDGES 600000
#define SCAN_BLOCKS ((N_NODES + 511) / 512)   // 98

// ---------------- scratch (device globals; zero-initialized at load) -----------
__device__ int      g_deg[N_NODES];
__device__ int      g_cnt2[N_NODES];
__device__ int      g_off[N_NODES + 1];
__device__ int      g_pos[N_NODES];
__device__ int      g_pos2[N_NODES];
__device__ int      g_blk_flag[SCAN_BLOCKS];
__device__ int      g_blk_aggv[SCAN_BLOCKS];
__device__ int      g_blk_pref[SCAN_BLOCKS];
__device__ int      g_csr[N_EDGES];
__device__ __half   g_x16 [(size_t)N_NODES * 128];
__device__ __half   g_agg16[(size_t)N_NODES * 256];
__device__ __half   g_h16 [(size_t)N_NODES * 256];
__device__ __half   g_y2  [(size_t)N_NODES * 256];
__device__ __half   g_w16 [262144];

#define OFF_W1L 0
#define OFF_W1R 32768
#define OFF_WS  65536
#define OFF_W2L 98304
#define OFF_W2R 163840
#define OFF_WO  229376

// ---------------- fast tanh ----------------------------------------------------
__device__ __forceinline__ float fast_tanh(float x) {
    float xc = fminf(fmaxf(x, -9.f), 9.f);
    float x2 = xc * xc;
    float p = fmaf(x2, -2.76076847742355e-16f, 2.00018790482477e-13f);
    p = fmaf(p, x2, -8.60467152213735e-11f);
    p = fmaf(p, x2, 5.12229709037114e-08f);
    p = fmaf(p, x2, 1.48572235717979e-05f);
    p = fmaf(p, x2, 6.37261928875436e-04f);
    p = fmaf(p, x2, 4.89352455891786e-03f);
    p = p * xc;
    float q = fmaf(x2, 1.19825839466702e-06f, 1.18534705686654e-04f);
    q = fmaf(q, x2, 2.26843463243900e-03f);
    q = fmaf(q, x2, 4.89352518554385e-03f);
    return __fdividef(p, q);
}

// ---------------- end-of-graph counter reset (runs on sB, overlaps layer2) ------
__global__ void reset_kernel() {
    int i = blockIdx.x * blockDim.x + threadIdx.x;
    if (i < N_NODES) { g_deg[i] = 0; g_cnt2[i] = 0; }
    if (i < SCAN_BLOCKS) g_blk_flag[i] = 0;
}

__global__ void prep_x_kernel(const float* __restrict__ x) {
    int tid = blockIdx.x * blockDim.x + threadIdx.x;
    int tot = gridDim.x * blockDim.x;
    for (int i = tid; i < N_NODES * 128 / 4; i += tot) {
        float4 v = ((const float4*)x)[i];
        __half2* d = (__half2*)(g_x16 + (size_t)i * 4);
        d[0] = __floats2half2_rn(v.x, v.y);
        d[1] = __floats2half2_rn(v.z, v.w);
    }
}

__global__ void prep_w_kernel(const float* __restrict__ W1l, const float* __restrict__ W1r,
                              const float* __restrict__ Ws,  const float* __restrict__ W2l,
                              const float* __restrict__ W2r, const float* __restrict__ Wo) {
    int tid = blockIdx.x * blockDim.x + threadIdx.x;
    int tot = gridDim.x * blockDim.x;
    const float* srcs[6] = {W1l, W1r, Ws, W2l, W2r, Wo};
    const int    lens[6] = {32768, 32768, 32768, 65536, 65536, 32768};
    const int    offs[6] = {OFF_W1L, OFF_W1R, OFF_WS, OFF_W2L, OFF_W2R, OFF_WO};
#pragma unroll
    for (int s = 0; s < 6; s++) {
        const float4* sp = (const float4*)srcs[s];
        __half2* dp = (__half2*)(g_w16 + offs[s]);
        for (int i = tid; i < lens[s] / 4; i += tot) {
            float4 v = sp[i];
            dp[i * 2]     = __floats2half2_rn(v.x, v.y);
            dp[i * 2 + 1] = __floats2half2_rn(v.z, v.w);
        }
    }
}

// ---------------- CSR build -----------------------------------------------------
__global__ void count_kernel(const int* __restrict__ dst, const unsigned* __restrict__ mask) {
    int e = blockIdx.x * blockDim.x + threadIdx.x;
    if (e >= N_EDGES) return;
    int d = dst[e];
    atomicAdd(&g_deg[d], 1);
    if (mask[e] != 0u) atomicAdd(&g_cnt2[d], 1);
}

__global__ void scan_kernel() {
    __shared__ int sh[512];
    __shared__ int s_prev;
    int b = blockIdx.x, tid = threadIdx.x;
    int i = b * 512 + tid;
    int v = (i < N_NODES) ? g_deg[i] : 0;
    sh[tid] = v;
    __syncthreads();
    for (int o = 1; o < 512; o <<= 1) {
        int t = (tid >= o) ? sh[tid - o] : 0;
        __syncthreads();
        sh[tid] += t;
        __syncthreads();
    }
    int total = sh[511];

    if (tid < 32) {
        if (b == 0) {
            if (tid == 0) {
                g_blk_pref[0] = total;
                __threadfence();
                *(volatile int*)&g_blk_flag[0] = 2;
                s_prev = 0;
            }
        } else {
            if (tid == 0) {
                g_blk_aggv[b] = total;
                __threadfence();
                *(volatile int*)&g_blk_flag[b] = 1;
            }
            int run = 0;
            int base = b;
            while (true) {
                int j = base - 32 + tid;
                int f;
                do {
                    f = (j >= 0) ? *(volatile int*)&g_blk_flag[j] : 2;
                } while (__any_sync(0xffffffffu, f == 0));
                __threadfence();
                unsigned pmask = __ballot_sync(0xffffffffu, f == 2);
                if (pmask) {
                    int hi = 31 - __clz(pmask);
                    int contrib = 0;
                    if (tid == hi)      contrib = (j >= 0) ? g_blk_pref[j] : 0;
                    else if (tid > hi)  contrib = g_blk_aggv[j];
#pragma unroll
                    for (int o = 16; o; o >>= 1) contrib += __shfl_xor_sync(0xffffffffu, contrib, o);
                    run += contrib;
                    break;
                } else {
                    int contrib = (j >= 0) ? g_blk_aggv[j] : 0;
#pragma unroll
                    for (int o = 16; o; o >>= 1) contrib += __shfl_xor_sync(0xffffffffu, contrib, o);
                    run += contrib;
                    base -= 32;
                }
            }
            if (tid == 0) {
                g_blk_pref[b] = run + total;
                __threadfence();
                *(volatile int*)&g_blk_flag[b] = 2;
                s_prev = run;
            }
        }
    }
    __syncthreads();
    int excl = s_prev + sh[tid] - v;
    if (i < N_NODES) {
        g_off[i]  = excl;
        g_pos[i]  = excl;
        g_pos2[i] = excl + g_cnt2[i];
    }
    if (b == 0 && tid == 0) g_off[N_NODES] = N_EDGES;
}

__global__ void scatter_kernel(const int* __restrict__ src, const int* __restrict__ dst,
                               const unsigned* __restrict__ mask) {
    int e = blockIdx.x * blockDim.x + threadIdx.x;
    if (e >= N_EDGES) return;
    int d = dst[e];
    int slot;
    if (mask[e] != 0u) slot = atomicAdd(&g_pos[d], 1);
    else               slot = atomicAdd(&g_pos2[d], 1);
    g_csr[slot] = src[e];
}

// ---------------- aggregation (warp per node, fp16 gather, MLP=4) ---------------
__global__ void agg1_kernel() {
    int w    = (blockIdx.x * blockDim.x + threadIdx.x) >> 5;
    int lane = threadIdx.x & 31;
    if (w >= N_NODES) return;
    int beg = g_off[w], end = g_off[w + 1];
    float4 acc0 = make_float4(0.f, 0.f, 0.f, 0.f);
    float4 acc1 = make_float4(0.f, 0.f, 0.f, 0.f);
    int p = beg;
    for (; p + 4 <= end; p += 4) {
        int s0 = g_csr[p], s1 = g_csr[p + 1], s2 = g_csr[p + 2], s3 = g_csr[p + 3];
        uint2 t0 = *(const uint2*)(g_x16 + (size_t)s0 * 128 + lane * 4);
        uint2 t1 = *(const uint2*)(g_x16 + (size_t)s1 * 128 + lane * 4);
        uint2 t2 = *(const uint2*)(g_x16 + (size_t)s2 * 128 + lane * 4);
        uint2 t3 = *(const uint2*)(g_x16 + (size_t)s3 * 128 + lane * 4);
        float2 f;
        f = __half22float2(*(__half2*)&t0.x); acc0.x += f.x; acc0.y += f.y;
        f = __half22float2(*(__half2*)&t0.y); acc0.z += f.x; acc0.w += f.y;
        f = __half22float2(*(__half2*)&t1.x); acc1.x += f.x; acc1.y += f.y;
        f = __half22float2(*(__half2*)&t1.y); acc1.z += f.x; acc1.w += f.y;
        f = __half22float2(*(__half2*)&t2.x); acc0.x += f.x; acc0.y += f.y;
        f = __half22float2(*(__half2*)&t2.y); acc0.z += f.x; acc0.w += f.y;
        f = __half22float2(*(__half2*)&t3.x); acc1.x += f.x; acc1.y += f.y;
        f = __half22float2(*(__half2*)&t3.y); acc1.z += f.x; acc1.w += f.y;
    }
    for (; p < end; p++) {
        int s0 = g_csr[p];
        uint2 t0 = *(const uint2*)(g_x16 + (size_t)s0 * 128 + lane * 4);
        float2 f;
        f = __half22float2(*(__half2*)&t0.x); acc0.x += f.x; acc0.y += f.y;
        f = __half22float2(*(__half2*)&t0.y); acc0.z += f.x; acc0.w += f.y;
    }
    int deg = end - beg;
    float inv = 1.0f / (float)(deg > 1 ? deg : 1);
    __half2 o0 = __floats2half2_rn((acc0.x + acc1.x) * inv, (acc0.y + acc1.y) * inv);
    __half2 o1 = __floats2half2_rn((acc0.z + acc1.z) * inv, (acc0.w + acc1.w) * inv);
    uint2 o; o.x = *(unsigned*)&o0; o.y = *(unsigned*)&o1;
    *(uint2*)(g_agg16 + (size_t)w * 128 + lane * 4) = o;
}

__global__ void agg2_kernel() {
    int w    = (blockIdx.x * blockDim.x + threadIdx.x) >> 5;
    int lane = threadIdx.x & 31;
    if (w >= N_NODES) return;
    int beg = g_off[w];
    int c   = g_cnt2[w];
    int end = beg + c;
    float a0[8], a1[8];
#pragma unroll
    for (int j = 0; j < 8; j++) { a0[j] = 0.f; a1[j] = 0.f; }
    int p = beg;
    for (; p + 4 <= end; p += 4) {
        int s0 = g_csr[p], s1 = g_csr[p + 1], s2 = g_csr[p + 2], s3 = g_csr[p + 3];
        uint4 t0 = *(const uint4*)(g_h16 + (size_t)s0 * 256 + lane * 8);
        uint4 t1 = *(const uint4*)(g_h16 + (size_t)s1 * 256 + lane * 8);
        uint4 t2 = *(const uint4*)(g_h16 + (size_t)s2 * 256 + lane * 8);
        uint4 t3 = *(const uint4*)(g_h16 + (size_t)s3 * 256 + lane * 8);
        float2 f;
        f = __half22float2(*(__half2*)&t0.x); a0[0] += f.x; a0[1] += f.y;
        f = __half22float2(*(__half2*)&t0.y); a0[2] += f.x; a0[3] += f.y;
        f = __half22float2(*(__half2*)&t0.z); a0[4] += f.x; a0[5] += f.y;
        f = __half22float2(*(__half2*)&t0.w); a0[6] += f.x; a0[7] += f.y;
        f = __half22float2(*(__half2*)&t1.x); a1[0] += f.x; a1[1] += f.y;
        f = __half22float2(*(__half2*)&t1.y); a1[2] += f.x; a1[3] += f.y;
        f = __half22float2(*(__half2*)&t1.z); a1[4] += f.x; a1[5] += f.y;
        f = __half22float2(*(__half2*)&t1.w); a1[6] += f.x; a1[7] += f.y;
        f = __half22float2(*(__half2*)&t2.x); a0[0] += f.x; a0[1] += f.y;
        f = __half22float2(*(__half2*)&t2.y); a0[2] += f.x; a0[3] += f.y;
        f = __half22float2(*(__half2*)&t2.z); a0[4] += f.x; a0[5] += f.y;
        f = __half22float2(*(__half2*)&t2.w); a0[6] += f.x; a0[7] += f.y;
        f = __half22float2(*(__half2*)&t3.x); a1[0] += f.x; a1[1] += f.y;
        f = __half22float2(*(__half2*)&t3.y); a1[2] += f.x; a1[3] += f.y;
        f = __half22float2(*(__half2*)&t3.z); a1[4] += f.x; a1[5] += f.y;
        f = __half22float2(*(__half2*)&t3.w); a1[6] += f.x; a1[7] += f.y;
    }
    for (; p < end; p++) {
        int s0 = g_csr[p];
        uint4 t0 = *(const uint4*)(g_h16 + (size_t)s0 * 256 + lane * 8);
        float2 f;
        f = __half22float2(*(__half2*)&t0.x); a0[0] += f.x; a0[1] += f.y;
        f = __half22float2(*(__half2*)&t0.y); a0[2] += f.x; a0[3] += f.y;
        f = __half22float2(*(__half2*)&t0.z); a0[4] += f.x; a0[5] += f.y;
        f = __half22float2(*(__half2*)&t0.w); a0[6] += f.x; a0[7] += f.y;
    }
    float inv = 1.0f / (float)(c > 1 ? c : 1);
    __half2 o0 = __floats2half2_rn((a0[0] + a1[0]) * inv, (a0[1] + a1[1]) * inv);
    __half2 o1 = __floats2half2_rn((a0[2] + a1[2]) * inv, (a0[3] + a1[3]) * inv);
    __half2 o2 = __floats2half2_rn((a0[4] + a1[4]) * inv, (a0[5] + a1[5]) * inv);
    __half2 o3 = __floats2half2_rn((a0[6] + a1[6]) * inv, (a0[7] + a1[7]) * inv);
    uint4 o;
    o.x = *(unsigned*)&o0; o.y = *(unsigned*)&o1;
    o.z = *(unsigned*)&o2; o.w = *(unsigned*)&o3;
    *(uint4*)(g_agg16 + (size_t)w * 256 + lane * 8) = o;
}

// ---------------- mma helpers ----------------------------------------------------
__device__ __forceinline__ void mma16(float* d, const unsigned* a, const unsigned* b) {
    asm volatile(
        "mma.sync.aligned.m16n8k16.row.col.f32.f16.f16.f32 "
        "{%0,%1,%2,%3}, {%4,%5,%6,%7}, {%8,%9}, {%0,%1,%2,%3};"
        : "+f"(d[0]), "+f"(d[1]), "+f"(d[2]), "+f"(d[3])
        : "r"(a[0]), "r"(a[1]), "r"(a[2]), "r"(a[3]), "r"(b[0]), "r"(b[1]));
}

__device__ __forceinline__ void ldsm4(unsigned* r, uint32_t addr) {
    asm volatile("ldmatrix.sync.aligned.m8n8.x4.shared.b16 {%0,%1,%2,%3}, [%4];"
        : "=r"(r[0]), "=r"(r[1]), "=r"(r[2]), "=r"(r[3]) : "r"(addr));
}

__device__ __forceinline__ uint32_t smem_u32(const void* p) {
    uint32_t a;
    asm("{ .reg .u64 t; cvta.to.shared.u64 t, %1; cvt.u32.u64 %0, t; }" : "=r"(a) : "l"(p));
    return a;
}

__device__ __forceinline__ void cp16(uint32_t dst, const void* src) {
    asm volatile("cp.async.cg.shared.global [%0], [%1], 16;" :: "r"(dst), "l"(src));
}
__device__ __forceinline__ void cp16z(uint32_t dst, const void* src, int sz) {
    asm volatile("cp.async.cg.shared.global [%0], [%1], 16, %2;" :: "r"(dst), "l"(src), "r"(sz));
}
#define CP_COMMIT() asm volatile("cp.async.commit_group;" ::: "memory")
#define CP_WAIT(n)  asm volatile("cp.async.wait_group %0;" :: "n"(n) : "memory")

#define STG_HALVES 55296
#define STG_A2     9216
#define STG_WL     18432
#define STG_WR     36864
#define FUSE_RS    264
#define FUSE_WO_OFF 67584

__device__ __forceinline__ void cpA128(uint32_t sbase, const __half* __restrict__ g,
                                       int ld, int k0, int row0) {
    int tid = threadIdx.x;
#pragma unroll
    for (int it = 0; it < 2; it++) {
        int idx = it * 512 + tid;
        int r = idx >> 3, cg = idx & 7;
        int gr = row0 + r;
        int rr = gr < N_NODES ? gr : N_NODES - 1;
        int sz = gr < N_NODES ? 16 : 0;
        cp16z(sbase + (r * 72 + cg * 8) * 2, g + (size_t)rr * ld + k0 + cg * 8, sz);
    }
}
__device__ __forceinline__ void cpW256(uint32_t sbase, const __half* __restrict__ g,
                                       int ld, int k0) {
    int tid = threadIdx.x;
#pragma unroll
    for (int it = 0; it < 4; it++) {
        int idx = it * 512 + tid;
        int r = idx >> 3, cg = idx & 7;
        cp16(sbase + (r * 72 + cg * 8) * 2, g + (size_t)r * ld + k0 + cg * 8);
    }
}

// ---------------- fused SAGE layer: 128x256 tile, 512 thr ------------------------
template <bool ADD_Y2, int NCH, bool FUSE_OUT>
__global__ __launch_bounds__(512, 1) void layer_fused2(
    const __half* __restrict__ A1, int ldA1, const __half* __restrict__ A2, int ldA2, int K,
    const __half* __restrict__ Wl, const __half* __restrict__ Wr,
    const float* __restrict__ bias,
    const __half* __restrict__ Y2, __half* __restrict__ H,
    const __half* __restrict__ Wo, const float* __restrict__ bo,
    float* __restrict__ O)
{
    extern __shared__ char smraw[];
    float*  sB    = (float*)smraw;
    float*  sred  = sB + 256;
    float*  sBO   = sred + 512;
    __half* stg   = (__half*)(sBO + 128);
    uint32_t stg_u = smem_u32(stg);

    int tid = threadIdx.x, lane = tid & 31, w = tid >> 5;
    int wm = w >> 2, wn = w & 3;
    int g = lane >> 2, t = lane & 3;
    int row0 = blockIdx.x * 128;

    if (tid < 256) sB[tid] = bias[tid];
    if (FUSE_OUT && tid < 128) sBO[tid] = bo[tid];

    float acc[2][8][4];
#pragma unroll
    for (int mt = 0; mt < 2; mt++)
#pragma unroll
        for (int nt = 0; nt < 8; nt++)
#pragma unroll
            for (int j = 0; j < 4; j++) acc[mt][nt][j] = 0.f;

    int aRow = 32 * wm + (lane & 15);
    int aCol = (lane >> 4) * 8;
    int bRow = 64 * wn + (lane & 7) + ((lane >> 4) << 3);
    int bCol = ((lane >> 3) & 1) * 8;

    cpA128(stg_u, A1, ldA1, 0, row0);
    cpA128(stg_u + STG_A2 * 2, A2, ldA2, 0, row0);
    cpW256(stg_u + STG_WL * 2, Wl, K, 0);
    cpW256(stg_u + STG_WR * 2, Wr, K, 0);
    CP_COMMIT();

#pragma unroll
    for (int c = 0; c < NCH; c++) {
        uint32_t cur = stg_u + (c & 1) * STG_HALVES * 2;
        if (c + 1 < NCH) {
            uint32_t nxt = stg_u + ((c + 1) & 1) * STG_HALVES * 2;
            int k0 = (c + 1) << 6;
            cpA128(nxt, A1, ldA1, k0, row0);
            cpA128(nxt + STG_A2 * 2, A2, ldA2, k0, row0);
            cpW256(nxt + STG_WL * 2, Wl, K, k0);
            cpW256(nxt + STG_WR * 2, Wr, K, k0);
            CP_COMMIT();
            CP_WAIT(1);
        } else {
            CP_WAIT(0);
        }
        __syncthreads();

#pragma unroll
        for (int ks = 0; ks < 4; ks++) {
            unsigned a1f[2][4], a2f[2][4];
#pragma unroll
            for (int mt = 0; mt < 2; mt++) {
                uint32_t ad = cur + ((aRow + 16 * mt) * 72 + ks * 16 + aCol) * 2;
                ldsm4(a1f[mt], ad);
                ldsm4(a2f[mt], ad + STG_A2 * 2);
            }
#pragma unroll
            for (int ng = 0; ng < 4; ng++) {
                unsigned bl[4], br[4];
                uint32_t bd = cur + ((bRow + 16 * ng) * 72 + ks * 16 + bCol) * 2;
                ldsm4(bl, bd + STG_WL * 2);
                ldsm4(br, bd + STG_WR * 2);
#pragma unroll
                for (int half = 0; half < 2; half++) {
                    int nt = 2 * ng + half;
                    mma16(acc[0][nt], a1f[0], bl + 2 * half);
                    mma16(acc[0][nt], a2f[0], br + 2 * half);
                    mma16(acc[1][nt], a1f[1], bl + 2 * half);
                    mma16(acc[1][nt], a2f[1], br + 2 * half);
                }
            }
        }
        __syncthreads();
    }

    if (FUSE_OUT) {
#pragma unroll
        for (int it = 0; it < 8; it++) {
            int idx = it * 512 + tid;
            int r = idx >> 5, cg = idx & 31;
            cp16(stg_u + FUSE_WO_OFF + (r * FUSE_RS + cg * 8) * 2,
                 Wo + (size_t)r * 256 + cg * 8);
        }
        CP_COMMIT();
    }

#pragma unroll
    for (int mt = 0; mt < 2; mt++) {
        float s0 = 0.f, s1 = 0.f;
#pragma unroll
        for (int nt = 0; nt < 8; nt++) {
            int col = 64 * wn + 8 * nt + 2 * t;
            acc[mt][nt][0] += sB[col];
            acc[mt][nt][1] += sB[col + 1];
            acc[mt][nt][2] += sB[col];
            acc[mt][nt][3] += sB[col + 1];
            s0 += acc[mt][nt][0] * acc[mt][nt][0] + acc[mt][nt][1] * acc[mt][nt][1];
            s1 += acc[mt][nt][2] * acc[mt][nt][2] + acc[mt][nt][3] * acc[mt][nt][3];
        }
        s0 += __shfl_xor_sync(0xffffffffu, s0, 1);
        s0 += __shfl_xor_sync(0xffffffffu, s0, 2);
        s1 += __shfl_xor_sync(0xffffffffu, s1, 1);
        s1 += __shfl_xor_sync(0xffffffffu, s1, 2);
        if (t == 0) {
            int r = 32 * wm + 16 * mt + g;
            sred[r * 4 + wn] = s0;
            sred[(r + 8) * 4 + wn] = s1;
        }
    }
    __syncthreads();

#pragma unroll
    for (int mt = 0; mt < 2; mt++) {
        int r0 = 32 * wm + 16 * mt + g, r1 = r0 + 8;
        float n0 = sred[r0 * 4] + sred[r0 * 4 + 1] + sred[r0 * 4 + 2] + sred[r0 * 4 + 3];
        float n1 = sred[r1 * 4] + sred[r1 * 4 + 1] + sred[r1 * 4 + 2] + sred[r1 * 4 + 3];
        float inv0 = rsqrtf(fmaxf(n0, 1e-24f));
        float inv1 = rsqrtf(fmaxf(n1, 1e-24f));
        int gr0 = row0 + r0, gr1 = row0 + r1;
#pragma unroll
        for (int nt = 0; nt < 8; nt++) {
            int col = 64 * wn + 8 * nt + 2 * t;
            float v0 = acc[mt][nt][0] * inv0, v1 = acc[mt][nt][1] * inv0;
            float v2 = acc[mt][nt][2] * inv1, v3 = acc[mt][nt][3] * inv1;
            if (ADD_Y2) {
                if (gr0 < N_NODES) {
                    float2 f = __half22float2(*(const __half2*)(Y2 + (size_t)gr0 * 256 + col));
                    v0 += f.x; v1 += f.y;
                }
                if (gr1 < N_NODES) {
                    float2 f = __half22float2(*(const __half2*)(Y2 + (size_t)gr1 * 256 + col));
                    v2 += f.x; v3 += f.y;
                }
            }
            __half2 o01 = __floats2half2_rn(fast_tanh(v0), fast_tanh(v1));
            __half2 o23 = __floats2half2_rn(fast_tanh(v2), fast_tanh(v3));
            if (FUSE_OUT) {
                *(__half2*)((char*)stg + (r0 * FUSE_RS + col) * 2) = o01;
                *(__half2*)((char*)stg + (r1 * FUSE_RS + col) * 2) = o23;
            } else {
                if (gr0 < N_NODES) *(__half2*)(H + (size_t)gr0 * 256 + col) = o01;
                if (gr1 < N_NODES) *(__half2*)(H + (size_t)gr1 * 256 + col) = o23;
            }
        }
    }

    if (FUSE_OUT) {
        CP_WAIT(0);
        __syncthreads();

        float acc2[2][4][4];
#pragma unroll
        for (int mt = 0; mt < 2; mt++)
#pragma unroll
            for (int nt = 0; nt < 4; nt++)
#pragma unroll
                for (int j = 0; j < 4; j++) acc2[mt][nt][j] = 0.f;

        int bRow2 = 32 * wn + (lane & 7) + ((lane >> 4) << 3);
        int bCol2 = ((lane >> 3) & 1) * 8;

#pragma unroll
        for (int ks = 0; ks < 16; ks++) {
            unsigned af[2][4];
#pragma unroll
            for (int mt = 0; mt < 2; mt++)
                ldsm4(af[mt], stg_u + ((aRow + 16 * mt) * FUSE_RS + ks * 16 + aCol) * 2);
#pragma unroll
            for (int ng = 0; ng < 2; ng++) {
                unsigned bf[4];
                ldsm4(bf, stg_u + FUSE_WO_OFF +
                          ((bRow2 + 16 * ng) * FUSE_RS + ks * 16 + bCol2) * 2);
#pragma unroll
                for (int half = 0; half < 2; half++) {
                    int nt = 2 * ng + half;
                    mma16(acc2[0][nt], af[0], bf + 2 * half);
                    mma16(acc2[1][nt], af[1], bf + 2 * half);
                }
            }
        }

#pragma unroll
        for (int mt = 0; mt < 2; mt++) {
            int gr0 = row0 + 32 * wm + 16 * mt + g, gr1 = gr0 + 8;
#pragma unroll
            for (int nt = 0; nt < 4; nt++) {
                int col = 32 * wn + 8 * nt + 2 * t;
                float b0 = sBO[col], b1 = sBO[col + 1];
                if (gr0 < N_NODES)
                    *(float2*)(O + (size_t)gr0 * 128 + col) =
                        make_float2(acc2[mt][nt][0] + b0, acc2[mt][nt][1] + b1);
                if (gr1 < N_NODES)
                    *(float2*)(O + (size_t)gr1 * 128 + col) =
                        make_float2(acc2[mt][nt][2] + b0, acc2[mt][nt][3] + b1);
            }
        }
    }
}

// ---------------- legacy smem loader for skip ------------------------------------
template <int ROWS>
__device__ __forceinline__ void load16(__half* s, const __half* __restrict__ g,
                                       int ld, int k0, int row0, int maxrow) {
    int tid = threadIdx.x;
#pragma unroll
    for (int it = 0; it < ROWS / 32; ++it) {
        int idx = it * 256 + tid;
        int r = idx >> 3, sg = idx & 7;
        uint4 v = make_uint4(0, 0, 0, 0);
        if (row0 + r < maxrow) v = *(const uint4*)(g + (size_t)(row0 + r) * ld + k0 + sg * 8);
        *(uint4*)(s + r * 72 + sg * 8) = v;
    }
}

// ---------------- skip GEMM (off-path) -------------------------------------------
__global__ __launch_bounds__(256, 2) void skip_mma(
    const __half* __restrict__ A, const __half* __restrict__ W,
    const float* __restrict__ bias, __half* __restrict__ Y)
{
    extern __shared__ char smraw[];
    float*  sB = (float*)smraw;
    __half* sA = (__half*)(sB + 256);
    __half* sW = sA + 64 * 72;

    int tid = threadIdx.x, lane = tid & 31, w = tid >> 5;
    int wm = w >> 2, wn = w & 3;
    int g = lane >> 2, t = lane & 3;
    int row0 = blockIdx.x * 64;
    const int K = 128;

    if (tid < 256) sB[tid] = bias[tid];

    float acc[2][8][4];
#pragma unroll
    for (int mt = 0; mt < 2; mt++)
#pragma unroll
        for (int nt = 0; nt < 8; nt++)
#pragma unroll
            for (int j = 0; j < 4; j++) acc[mt][nt][j] = 0.f;

    for (int c = 0; c < 2; c++) {
        int k0 = c << 6;
        load16<64>(sA, A, K, k0, row0, N_NODES);
        load16<256>(sW, W, K, k0, 0, 256);
        __syncthreads();
        const unsigned* uA = (const unsigned*)sA;
        const unsigned* uW = (const unsigned*)sW;
#pragma unroll
        for (int ks = 0; ks < 4; ks++) {
            int wb = ks * 8 + t;
            unsigned af[2][4];
#pragma unroll
            for (int mt = 0; mt < 2; mt++) {
                int r = 32 * wm + 16 * mt + g;
                af[mt][0] = uA[r * 36 + wb];
                af[mt][1] = uA[(r + 8) * 36 + wb];
                af[mt][2] = uA[r * 36 + wb + 4];
                af[mt][3] = uA[(r + 8) * 36 + wb + 4];
            }
#pragma unroll
            for (int nt = 0; nt < 8; nt++) {
                int n = 64 * wn + 8 * nt + g;
                unsigned bf[2];
                bf[0] = uW[n * 36 + wb]; bf[1] = uW[n * 36 + wb + 4];
                mma16(acc[0][nt], af[0], bf);
                mma16(acc[1][nt], af[1], bf);
            }
        }
        __syncthreads();
    }

#pragma unroll
    for (int mt = 0; mt < 2; mt++) {
        int gr0 = row0 + 32 * wm + 16 * mt + g, gr1 = gr0 + 8;
#pragma unroll
        for (int nt = 0; nt < 8; nt++) {
            int col = 64 * wn + 8 * nt + 2 * t;
            float b0 = sB[col], b1 = sB[col + 1];
            if (gr0 < N_NODES) {
                *(__half2*)(Y + (size_t)gr0 * 256 + col) =
                    __floats2half2_rn(acc[mt][nt][0] + b0, acc[mt][nt][1] + b1);
            }
            if (gr1 < N_NODES) {
                *(__half2*)(Y + (size_t)gr1 * 256 + col) =
                    __floats2half2_rn(acc[mt][nt][2] + b0, acc[mt][nt][3] + b1);
            }
        }
    }
}

// ---------------- launch ----------------------------------------------------------
extern "C" void kernel_launch(void* const* d_in, const int* in_sizes, int n_in,
                              void* d_out, int out_size)
{
    (void)in_sizes; (void)n_in; (void)out_size;
    const float*    x    = (const float*)d_in[0];
    const int*      ei   = (const int*)d_in[1];
    const unsigned* mask = (const unsigned*)d_in[2];
    const float*    W1l  = (const float*)d_in[3];
    const float*    b1   = (const float*)d_in[4];
    const float*    W1r  = (const float*)d_in[5];
    const float*    Ws   = (const float*)d_in[6];
    const float*    bs   = (const float*)d_in[7];
    const float*    W2l  = (const float*)d_in[8];
    const float*    b2   = (const float*)d_in[9];
    const float*    W2r  = (const float*)d_in[10];
    const float*    Wo   = (const float*)d_in[11];
    const float*    bo   = (const float*)d_in[12];
    float*          out  = (float*)d_out;

    const int* src = ei;
    const int* dst = ei + N_EDGES;

    void *p_x16, *p_agg, *p_h, *p_y2, *p_w;
    cudaGetSymbolAddress(&p_x16, g_x16);
    cudaGetSymbolAddress(&p_agg, g_agg16);
    cudaGetSymbolAddress(&p_h,   g_h16);
    cudaGetSymbolAddress(&p_y2,  g_y2);
    cudaGetSymbolAddress(&p_w,   g_w16);
    __half* x16 = (__half*)p_x16;
    __half* agg = (__half*)p_agg;
    __half* h   = (__half*)p_h;
    __half* y2  = (__half*)p_y2;
    __half* w16 = (__half*)p_w;

    static cudaStream_t sB = nullptr;
    static cudaEvent_t evFork = nullptr, evSkip = nullptr, evA2 = nullptr, evReset = nullptr;
    if (!sB) {
        cudaStreamCreateWithFlags(&sB, cudaStreamNonBlocking);
        cudaEventCreateWithFlags(&evFork,  cudaEventDisableTiming);
        cudaEventCreateWithFlags(&evSkip,  cudaEventDisableTiming);
        cudaEventCreateWithFlags(&evA2,    cudaEventDisableTiming);
        cudaEventCreateWithFlags(&evReset, cudaEventDisableTiming);
    }

    const int SM_L2   = (256 + 512 + 128) * 4 + 2 * STG_HALVES * 2;
    const int SM_SKIP = 256 * 4 + (64 * 72 + 256 * 72) * 2;
    cudaFuncSetAttribute((const void*)layer_fused2<true, 2, false>,
                         cudaFuncAttributeMaxDynamicSharedMemorySize, SM_L2);
    cudaFuncSetAttribute((const void*)layer_fused2<false, 4, true>,
                         cudaFuncAttributeMaxDynamicSharedMemorySize, SM_L2);
    cudaFuncSetAttribute(skip_mma, cudaFuncAttributeMaxDynamicSharedMemorySize, SM_SKIP);

    int nb_nodes = (N_NODES + 255) / 256;
    int nb_edges = (N_EDGES + 255) / 256;
    int nb_warps = (N_NODES * 32 + 255) / 256;
    int nb_m64   = (N_NODES + 63) / 64;
    int nb_m128  = (N_NODES + 127) / 128;

    // fork: stream B does fp16 conversions + skip GEMM while stream 0 builds CSR
    cudaEventRecord(evFork, 0);
    cudaStreamWaitEvent(sB, evFork, 0);

    prep_x_kernel<<<512, 256, 0, sB>>>(x);
    prep_w_kernel<<<512, 256, 0, sB>>>(W1l, W1r, Ws, W2l, W2r, Wo);
    skip_mma<<<nb_m64, 256, SM_SKIP, sB>>>(x16, w16 + OFF_WS, bs, y2);
    cudaEventRecord(evSkip, sB);

    // stream 0: CSR build (counters zeroed by previous replay's reset / static init)
    count_kernel<<<nb_edges, 256>>>(dst, mask);
    scan_kernel<<<SCAN_BLOCKS, 512>>>();
    scatter_kernel<<<nb_edges, 256>>>(src, dst, mask);

    agg1_kernel<<<nb_warps, 256>>>();

    cudaStreamWaitEvent(0, evSkip, 0);
    layer_fused2<true, 2, false><<<nb_m128, 512, SM_L2>>>(
        agg, 128, x16, 128, 128, w16 + OFF_W1L, w16 + OFF_W1R, b1, y2, h,
        nullptr, nullptr, nullptr);

    agg2_kernel<<<nb_warps, 256>>>();
    cudaEventRecord(evA2, 0);

    // counters reset for next replay, off the critical path (overlaps layer2)
    cudaStreamWaitEvent(sB, evA2, 0);
    reset_kernel<<<nb_nodes, 256, 0, sB>>>();
    cudaEventRecord(evReset, sB);

    layer_fused2<false, 4, true><<<nb_m128, 512, SM_L2>>>(
        agg, 256, h, 256, 256, w16 + OFF_W2L, w16 + OFF_W2R, b2, nullptr, nullptr,
        w16 + OFF_WO, bo, out);

    // join sB back into the capture-origin stream (reset overlaps layer2)
    cudaStreamWaitEvent(0, evReset, 0);
}